// round 12
// baseline (speedup 1.0000x reference)
#include <cuda_runtime.h>
#include <cstdint>

// WanRotaryPosEmbedS2VStyle: build (freqs_cos, freqs_sin) grids.
//
//   output: cos (1, n_tok, 1, 128) then sin; n_tok = F*3600.
//   Per token (f,y,x): ch [0,44)=t_tab[pt], [44,86)=h_tab[y], [86,128)=w_tab[x].
//
// R12: X_PER sweep {1,4,10,12,20} -> {16.9,14.3,15.6,16.0,17.2}us; all
// well-occupied variants hit 81MB/14.3us = 5.66 TB/s = ~50% of LTS combined
// cap -> L2 store-path wall. This round: R3 (best point) with the one defect
// removed — w-table loads use base+immediate offsets (xi*W_DIM folded into
// LDG imm) instead of a serial pointer-increment chain, so all iterations'
// loads are independent and ptxas can pipeline them at its own register
// budget. Exact gathers (rel_err 0).

#define T_DIM 44
#define H_DIM 42
#define W_DIM 42
#define GRID_W 60
#define GRID_HW 3600
#define FIXED_REF 30
#define X_PER 4            // tokens per warp (divides 60) — measured optimum

__global__ __launch_bounds__(256)
void wan_rope_kernel(
    const float* __restrict__ tcos, const float* __restrict__ hcos,
    const float* __restrict__ wcos, const float* __restrict__ tsin,
    const float* __restrict__ hsin, const float* __restrict__ wsin,
    const int*   __restrict__ nvf_p,
    float* __restrict__ out, int n_tok, int n_warps)
{
    const int gtid = blockIdx.x * blockDim.x + threadIdx.x;
    const int w    = gtid >> 5;
    if (w >= n_warps) return;
    const int lane = gtid & 31;
    const int d0   = lane << 2;            // channels [d0, d0+4)

    const int tok0 = w * X_PER;            // X_PER tokens, same (f,y)
    const int f    = tok0 / GRID_HW;
    const int rem  = tok0 - f * GRID_HW;
    const int y    = rem / GRID_W;
    const int x0   = rem - y * GRID_W;

    const int video_pp = __ldg(nvf_p);
    const int pt = (f < video_pp) ? f : FIXED_REF;

    const int tbase = pt * T_DIM;
    const int hbase = y * H_DIM - T_DIM;
    const int wbase = x0 * W_DIM - (T_DIM + H_DIM);

    const int dA = d0;                     // first even pair
    const int dB = d0 + 2;                 // second even pair
    const bool iswA = (dA >= T_DIM + H_DIM);
    const bool iswB = (dB >= T_DIM + H_DIM);

    // fixed base pointers (never incremented -> loads are base+imm, independent)
    const float* pcA = iswA ? (wcos + wbase + dA)
                     : (dA >= T_DIM) ? (hcos + hbase + dA) : (tcos + tbase + dA);
    const float* psA = iswA ? (wsin + wbase + dA)
                     : (dA >= T_DIM) ? (hsin + hbase + dA) : (tsin + tbase + dA);
    const float* pcB = iswB ? (wcos + wbase + dB)
                     : (dB >= T_DIM) ? (hcos + hbase + dB) : (tcos + tbase + dB);
    const float* psB = iswB ? (wsin + wbase + dB)
                     : (dB >= T_DIM) ? (hsin + hbase + dB) : (tsin + tbase + dB);

    // token-0 values (also the constant value for non-w lanes)
    float2 cA = __ldg(reinterpret_cast<const float2*>(pcA));
    float2 sA = __ldg(reinterpret_cast<const float2*>(psA));
    float2 cB = __ldg(reinterpret_cast<const float2*>(pcB));
    float2 sB = __ldg(reinterpret_cast<const float2*>(psB));

    float4* oc4 = reinterpret_cast<float4*>(out + (size_t)tok0 * 128 + d0);
    float4* os4 = reinterpret_cast<float4*>(out + (size_t)(n_tok + tok0) * 128 + d0);

    oc4[0] = make_float4(cA.x, cA.y, cB.x, cB.y);
    os4[0] = make_float4(sA.x, sA.y, sB.x, sB.y);

#pragma unroll
    for (int xi = 1; xi < X_PER; xi++) {
        // independent loads (immediate offset xi*W_DIM, no pointer chain);
        // only w-lanes reload, others keep token-0 values.
        if (iswA) {
            cA = __ldg(reinterpret_cast<const float2*>(pcA + xi * W_DIM));
            sA = __ldg(reinterpret_cast<const float2*>(psA + xi * W_DIM));
        }
        if (iswB) {
            cB = __ldg(reinterpret_cast<const float2*>(pcB + xi * W_DIM));
            sB = __ldg(reinterpret_cast<const float2*>(psB + xi * W_DIM));
        }
        oc4[xi * 32] = make_float4(cA.x, cA.y, cB.x, cB.y);
        os4[xi * 32] = make_float4(sA.x, sA.y, sB.x, sB.y);
    }
}

extern "C" void kernel_launch(void* const* d_in, const int* in_sizes, int n_in,
                              void* d_out, int out_size)
{
    // 0: hidden_states (unused)
    // 1: freq_t_cos  2: freq_h_cos  3: freq_w_cos
    // 4: freq_t_sin  5: freq_h_sin  6: freq_w_sin
    // 7: num_video_frames (int32)   8: num_ref_frames (int32)
    const float* tcos = (const float*)d_in[1];
    const float* hcos = (const float*)d_in[2];
    const float* wcos = (const float*)d_in[3];
    const float* tsin = (const float*)d_in[4];
    const float* hsin = (const float*)d_in[5];
    const float* wsin = (const float*)d_in[6];
    const int*   nvf  = (const int*)d_in[7];

    float* out = (float*)d_out;

    const int n_tok   = out_size / 256;    // out_size = 2 * n_tok * 128
    const int n_warps = n_tok / X_PER;
    const int threads = 256;
    const int blocks  = (n_warps * 32 + threads - 1) / threads;

    wan_rope_kernel<<<blocks, threads>>>(tcos, hcos, wcos, tsin, hsin, wsin,
                                         nvf, out, n_tok, n_warps);
}